// round 6
// baseline (speedup 1.0000x reference)
#include <cuda_runtime.h>
#include <cuda_fp16.h>
#include <math.h>
#include <cstdint>

#define LL    4096
#define DD    64
#define MODES 64
#define BH    64
#define MM    128
#define NSPLIT 4
#define SCALE 0.125f

// ---------------- globals (no allocation) ----------------
__device__ int      g_perm[3][64];                  // parity-sorted mode order per tensor
__device__ int      g_sclass[3][4];                 // strip class: 0=even(Bp) 1=odd(Bm) 2=mixed
__device__ int      g_vmap[64];                     // sigma_v^-1 o sigma_k
__device__ uint32_t g_WfPHi[3][8][2][128][32][4];   // fwd basis frags (K=2048), variant 0/1
__device__ uint32_t g_WfPLo[3][8][2][128][32][4];
__device__ uint32_t g_WiPHi[256][8][32][4];         // inv basis frags (x1024 scaled)
__device__ uint32_t g_WiPLo[256][8][32][4];
__device__ float    g_F[3][NSPLIT][BH][MM][DD];     // split-K partials (storage mode order)
__device__ float    g_Ffin[3][BH][MM][DD];          // reduced spectra
__device__ float    g_V2[BH][MM][DD];               // post-attention values

// ---------------- helpers ----------------
__device__ __forceinline__ uint32_t packh(__half a, __half b) {
    return (uint32_t)__half_as_ushort(a) | ((uint32_t)__half_as_ushort(b) << 16);
}
__device__ __forceinline__ void split2h(float a, float b, uint32_t& h, uint32_t& l) {
    __half ha = __float2half_rn(a), hb = __float2half_rn(b);
    __half la = __float2half_rn(a - __half2float(ha));
    __half lb = __float2half_rn(b - __half2float(hb));
    h = packh(ha, hb);
    l = packh(la, lb);
}
__device__ __forceinline__ void mma16816h(float* c, const uint4& a, const uint2& b) {
    asm volatile(
        "mma.sync.aligned.m16n8k16.row.col.f32.f16.f16.f32 "
        "{%0,%1,%2,%3}, {%4,%5,%6,%7}, {%8,%9}, {%0,%1,%2,%3};"
        : "+f"(c[0]), "+f"(c[1]), "+f"(c[2]), "+f"(c[3])
        : "r"(a.x), "r"(a.y), "r"(a.z), "r"(a.w), "r"(b.x), "r"(b.y));
}

// ---------------- kernel 0: permutations (tiny, serial) ----------------
__global__ void perm_kernel(const int* __restrict__ iq,
                            const int* __restrict__ ik,
                            const int* __restrict__ iv) {
    if (threadIdx.x != 0) return;
    for (int t = 0; t < 3; t++) {
        const int* ix = (t == 0) ? iq : ((t == 1) ? ik : iv);
        int pm[64], ne = 0;
        for (int i = 0; i < 64; i++) if ((ix[i] & 1) == 0) pm[ne++] = i;
        int no = ne;
        for (int i = 0; i < 64; i++) if (ix[i] & 1) pm[no++] = i;
        for (int i = 0; i < 64; i++) g_perm[t][i] = pm[i];
        for (int s4 = 0; s4 < 4; s4++) {
            int st0 = s4 * 16, st1 = st0 + 15;
            g_sclass[t][s4] = (st1 < ne) ? 0 : ((st0 >= ne) ? 1 : 2);
        }
    }
    int ipv[64];
    for (int i = 0; i < 64; i++) ipv[g_perm[2][i]] = i;
    for (int s4 = 0; s4 < 64; s4++) g_vmap[s4] = ipv[g_perm[1][s4]];
}

// ---------------- kernel 1: build fragment-packed bases ----------------
#define FWDN (3 * 8 * 2 * 128 * 32 * 4)   // 786432
#define INVN (256 * 8 * 32 * 4)           // 262144

__device__ __forceinline__ float invv_p(int n, int k2) {
    int gq = g_perm[0][k2 & 63];    // frequency bin (permuted q-mode order), x1024 scale
    if (gq == 0) return (k2 < 64) ? (1024.0f / (float)LL) : 0.0f;
    int r = (gq * n) & (LL - 1);
    float s, c;
    sincospif((float)r * (1.0f / 2048.0f), &s, &c);
    return (k2 < 64) ? (2048.0f / (float)LL) * c : -(2048.0f / (float)LL) * s;
}

__global__ __launch_bounds__(256) void build_packed(const int* __restrict__ iq,
                                                    const int* __restrict__ ik,
                                                    const int* __restrict__ iv) {
    for (int gid = blockIdx.x * blockDim.x + threadIdx.x; gid < FWDN + INVN;
         gid += gridDim.x * blockDim.x) {
        if (gid < FWDN) {
            int r    = gid & 3;
            int lane = (gid >> 2) & 31;
            int ks   = (gid >> 7) & 127;
            int vv   = (gid >> 14) & 1;
            int s    = (gid >> 15) & 7;
            int t    = gid >> 18;
            int m_local = s * 16 + (r & 1) * 8 + (lane >> 2);
            int mode_st = m_local & 63;
            const int* ix = (t == 0) ? iq : ((t == 1) ? ik : iv);
            int f = ix[g_perm[t][mode_st]];
            float v0 = 0.0f, v1 = 0.0f;
            if ((f & 1) == vv) {
                int k = ks * 16 + ((r >> 1) & 1) * 8 + (lane & 3) * 2;
                int r1 = (f * k) & (LL - 1);
                int r2 = (r1 + f) & (LL - 1);
                float s1, c1, s2, c2;
                sincospif((float)r1 * (1.0f / 2048.0f), &s1, &c1);
                sincospif((float)r2 * (1.0f / 2048.0f), &s2, &c2);
                v0 = (m_local < MODES) ? c1 : -s1;
                v1 = (m_local < MODES) ? c2 : -s2;
            }
            uint32_t h, l;
            split2h(v0, v1, h, l);
            g_WfPHi[t][s][vv][ks][lane][r] = h;
            g_WfPLo[t][s][vv][ks][lane][r] = l;
        } else {
            int g2    = gid - FWDN;
            int r     = g2 & 3;
            int lane  = (g2 >> 2) & 31;
            int ks    = (g2 >> 7) & 7;
            int strip = g2 >> 10;
            int n  = strip * 16 + (r & 1) * 8 + (lane >> 2);
            int k2 = ks * 16 + ((r >> 1) & 1) * 8 + (lane & 3) * 2;
            float v0 = invv_p(n, k2);
            float v1 = invv_p(n, k2 + 1);
            uint32_t h, l;
            split2h(v0, v1, h, l);
            g_WiPHi[strip][ks][lane][r] = h;
            g_WiPLo[strip][ks][lane][r] = l;
        }
    }
}

// ---------------- kernel 2: forward DFT (fold-by-2, fp16 3-pass, double-buffered) --
// grid (NSPLIT, 64, 3), 256 threads = 8 warps; warp handles rotated strip s.
// Dynamic smem: 2 buffers x 4 arrays x [64][40] u32 = 81920 B.
#define FWD_BUF_WORDS 2560   // 64*40
__global__ __launch_bounds__(256) void fwd_mma(const float* __restrict__ q,
                                               const float* __restrict__ k_,
                                               const float* __restrict__ v_) {
    extern __shared__ uint32_t dsm[];
    const int split = blockIdx.x, bh = blockIdx.y, t = blockIdx.z;
    const float* xb = ((t == 0) ? q : ((t == 1) ? k_ : v_)) + (size_t)bh * LL * DD;
    const int tid = threadIdx.x, warp = tid >> 5, lane = tid & 31;
    const int g = lane >> 2, tq = lane & 3;
    const int s = (warp + bh + split) & 7;        // rotated strip -> SMSP load balance
    const int cls = g_sclass[t][s & 3];
    const int p = tid & 31, oct = tid >> 5;
    const int w = ((p >> 3) << 3) + ((p & 3) << 1) + ((p >> 2) & 1);

    // buffer base offsets (words): [buf][arr 0=BpH 1=BpL 2=BmH 3=BmL]
#define FBUF(buf, arr) (dsm + ((buf) * 4 + (arr)) * FWD_BUF_WORDS)

    float acc[8][4];
#pragma unroll
    for (int j = 0; j < 8; j++)
#pragma unroll
        for (int i = 0; i < 4; i++) acc[j][i] = 0.0f;

    float4 pf[8];
    // prologue: load + stage chunk 0 into buffer 0
    {
        const float* r00 = xb + (size_t)(split * 512 + 2 * p) * DD + oct * 8;
        const float* r10 = r00 + (size_t)2048 * DD;
        pf[0] = *(const float4*)(r00);
        pf[1] = *(const float4*)(r00 + 4);
        pf[2] = *(const float4*)(r00 + DD);
        pf[3] = *(const float4*)(r00 + DD + 4);
        pf[4] = *(const float4*)(r10);
        pf[5] = *(const float4*)(r10 + 4);
        pf[6] = *(const float4*)(r10 + DD);
        pf[7] = *(const float4*)(r10 + DD + 4);
        const float* al = (const float*)&pf[0];
        const float* bl = (const float*)&pf[2];
        const float* cl = (const float*)&pf[4];
        const float* dl = (const float*)&pf[6];
        uint32_t* BpH = FBUF(0, 0);
        uint32_t* BpL = FBUF(0, 1);
        uint32_t* BmH = FBUF(0, 2);
        uint32_t* BmL = FBUF(0, 3);
#pragma unroll
        for (int i = 0; i < 8; i++) {
            float a = ((i < 4) ? al[i] : al[i]) ;  // contiguous float view
            float b = bl[i], c = cl[i], d = dl[i];
            uint32_t h, l;
            int row = (oct * 8 + i) * 40 + w;
            split2h(a + c, b + d, h, l);
            BpH[row] = h; BpL[row] = l;
            split2h(a - c, b - d, h, l);
            BmH[row] = h; BmL[row] = l;
        }
    }
    __syncthreads();

    for (int ch = 0; ch < 8; ch++) {
        const int cur = ch & 1;
        const bool hasNext = (ch + 1 < 8);
        if (hasNext) {
            const int k0n = split * 512 + (ch + 1) * 64;
            const float* r00 = xb + (size_t)(k0n + 2 * p) * DD + oct * 8;
            const float* r10 = r00 + (size_t)2048 * DD;
            pf[0] = *(const float4*)(r00);
            pf[1] = *(const float4*)(r00 + 4);
            pf[2] = *(const float4*)(r00 + DD);
            pf[3] = *(const float4*)(r00 + DD + 4);
            pf[4] = *(const float4*)(r10);
            pf[5] = *(const float4*)(r10 + 4);
            pf[6] = *(const float4*)(r10 + DD);
            pf[7] = *(const float4*)(r10 + DD + 4);
        }
        // MMAs on current buffer
        const int ksg = split * 32 + ch * 4;
        const uint32_t* BpH = FBUF(cur, 0);
        const uint32_t* BpL = FBUF(cur, 1);
        const uint32_t* BmH = FBUF(cur, 2);
        const uint32_t* BmL = FBUF(cur, 3);
#pragma unroll
        for (int ks4 = 0; ks4 < 4; ks4++) {
            if (cls != 1) {
                uint4 aH = *(const uint4*)&g_WfPHi[t][s][0][ksg + ks4][lane][0];
                uint4 aL = *(const uint4*)&g_WfPLo[t][s][0][ksg + ks4][lane][0];
#pragma unroll
                for (int j = 0; j < 8; j++) {
                    uint2 bH = *(const uint2*)&BpH[(j * 8 + g) * 40 + ks4 * 8 + 2 * tq];
                    uint2 bL = *(const uint2*)&BpL[(j * 8 + g) * 40 + ks4 * 8 + 2 * tq];
                    mma16816h(acc[j], aH, bH);
                    mma16816h(acc[j], aH, bL);
                    mma16816h(acc[j], aL, bH);
                }
            }
            if (cls != 0) {
                uint4 aH = *(const uint4*)&g_WfPHi[t][s][1][ksg + ks4][lane][0];
                uint4 aL = *(const uint4*)&g_WfPLo[t][s][1][ksg + ks4][lane][0];
#pragma unroll
                for (int j = 0; j < 8; j++) {
                    uint2 bH = *(const uint2*)&BmH[(j * 8 + g) * 40 + ks4 * 8 + 2 * tq];
                    uint2 bL = *(const uint2*)&BmL[(j * 8 + g) * 40 + ks4 * 8 + 2 * tq];
                    mma16816h(acc[j], aH, bH);
                    mma16816h(acc[j], aH, bL);
                    mma16816h(acc[j], aL, bH);
                }
            }
        }
        // stage next chunk into the other buffer
        if (hasNext) {
            const float* al = (const float*)&pf[0];
            const float* bl = (const float*)&pf[2];
            const float* cl = (const float*)&pf[4];
            const float* dl = (const float*)&pf[6];
            uint32_t* nBpH = FBUF(cur ^ 1, 0);
            uint32_t* nBpL = FBUF(cur ^ 1, 1);
            uint32_t* nBmH = FBUF(cur ^ 1, 2);
            uint32_t* nBmL = FBUF(cur ^ 1, 3);
#pragma unroll
            for (int i = 0; i < 8; i++) {
                float a = al[i], b = bl[i], c = cl[i], d = dl[i];
                uint32_t h, l;
                int row = (oct * 8 + i) * 40 + w;
                split2h(a + c, b + d, h, l);
                nBpH[row] = h; nBpL[row] = l;
                split2h(a - c, b - d, h, l);
                nBmH[row] = h; nBmL[row] = l;
            }
        }
        __syncthreads();
    }
    const int m0 = s * 16;
#pragma unroll
    for (int j = 0; j < 8; j++) {
        float* dst = &g_F[t][split][bh][m0 + g][j * 8 + 2 * tq];
        *(float2*)dst = make_float2(acc[j][0], acc[j][1]);
        *(float2*)(dst + 8 * DD) = make_float2(acc[j][2], acc[j][3]);
    }
#undef FBUF
}

// ---------------- kernel 3: reduce split-K partials ----------------
__global__ __launch_bounds__(256) void reduce_kernel() {
    const int TOT = 3 * BH * MM * DD / 4;   // 393216 float4
    int i = blockIdx.x * blockDim.x + threadIdx.x;
    if (i >= TOT) return;
    const int PER_T = BH * MM * DD / 4;     // 131072
    int t = i / PER_T;
    int r = i - t * PER_T;
    const float4* base = (const float4*)&g_F[t][0][0][0][0];
    float4 a = base[r];
#pragma unroll
    for (int s = 1; s < NSPLIT; s++) {
        float4 b = base[s * PER_T + r];
        a.x += b.x; a.y += b.y; a.z += b.z; a.w += b.w;
    }
    ((float4*)g_Ffin)[i] = a;
}

// ---------------- kernel 4: complex attention (mode-split 4-way) ----------------
#define SP 65
__global__ __launch_bounds__(256) void attn_kernel() {
    extern __shared__ float sm[];
    float* Ks = sm;                 // [128][65]
    float* Vs = Ks + MM * SP;       // [128][65]
    float* Qs = Vs + MM * SP;       // [32][65]  (16 re rows + 16 im rows)
    float* SR = Qs + 32 * SP;       // [16][65]
    float* SI = SR + 16 * SP;       // [16][65]

    const int bh = blockIdx.x, ms = blockIdx.y;
    const int tid = threadIdx.x;

    for (int e = tid; e < MM * DD; e += 256) {
        const int r = e >> 6, d = e & 63;
        Ks[r * SP + d] = g_Ffin[1][bh][r][d];
        int vrow = ((r >= 64) ? 64 : 0) + __ldg(&g_vmap[r & 63]);
        Vs[r * SP + d] = g_Ffin[2][bh][vrow][d];
    }
    for (int e = tid; e < 32 * DD; e += 256) {
        const int r = e >> 6, d = e & 63;
        int qrow = (r < 16) ? (ms * 16 + r) : (64 + ms * 16 + (r - 16));
        Qs[r * SP + d] = g_Ffin[0][bh][qrow][d];
    }
    __syncthreads();

    const int tm = tid >> 4;   // mode row within this block's 16
    const int tn = tid & 15;   // 4-col group over 64 k-modes

    {
        float re[4], im[4];
#pragma unroll
        for (int j = 0; j < 4; j++) { re[j] = 0.f; im[j] = 0.f; }
        for (int d = 0; d < DD; d++) {
            float qr = Qs[tm * SP + d];
            float qi = Qs[(16 + tm) * SP + d];
#pragma unroll
            for (int j = 0; j < 4; j++) {
                float kr = Ks[(tn * 4 + j) * SP + d];
                float ki = Ks[(64 + tn * 4 + j) * SP + d];
                re[j] = fmaf(qr, kr, re[j]);
                re[j] = fmaf(-qi, ki, re[j]);
                im[j] = fmaf(qr, ki, im[j]);
                im[j] = fmaf(qi, kr, im[j]);
            }
        }
#pragma unroll
        for (int j = 0; j < 4; j++) {
            const float x  = re[j] * SCALE;
            const float y  = im[j] * SCALE;
            const float x2 = 2.0f * x;
            float tr, ti;
            if (fabsf(x2) > 80.0f) {
                tr = (x > 0.0f) ? 1.0f : -1.0f;
                ti = 0.0f;
            } else {
                const float y2 = 2.0f * y;
                const float dn = coshf(x2) + cosf(y2);
                tr = sinhf(x2) / dn;
                ti = sinf(y2) / dn;
            }
            SR[tm * SP + tn * 4 + j] = tr;
            SI[tm * SP + tn * 4 + j] = ti;
        }
    }
    __syncthreads();

    {
        float vr[4], vi[4];
#pragma unroll
        for (int j = 0; j < 4; j++) { vr[j] = 0.f; vi[j] = 0.f; }
        for (int n = 0; n < MODES; n++) {
            float sr = SR[tm * SP + n];
            float si = SI[tm * SP + n];
#pragma unroll
            for (int j = 0; j < 4; j++) {
                float br = Vs[n * SP + tn * 4 + j];
                float bi = Vs[(64 + n) * SP + tn * 4 + j];
                vr[j] = fmaf(sr, br, vr[j]);
                vr[j] = fmaf(-si, bi, vr[j]);
                vi[j] = fmaf(sr, bi, vi[j]);
                vi[j] = fmaf(si, br, vi[j]);
            }
        }
#pragma unroll
        for (int j = 0; j < 4; j++) {
            g_V2[bh][ms * 16 + tm][tn * 4 + j]      = vr[j];
            g_V2[bh][64 + ms * 16 + tm][tn * 4 + j] = vi[j];
        }
    }
}

// ---------------- kernel 5: inverse transform (fp16 3-pass) ----------------
#define ISC (1.0f / 1024.0f)
__global__ __launch_bounds__(256) void inv_mma(float* __restrict__ out) {
    __shared__ uint32_t BsH[64][72];
    __shared__ uint32_t BsL[64][72];
    const int nt = blockIdx.x, bh = blockIdx.y;
    const int tid = threadIdx.x, warp = tid >> 5, lane = tid & 31;
    const int g = lane >> 2, tq = lane & 3;

    {
        const int pr = tid & 63, quad = tid >> 6;
        const int w = ((pr >> 3) << 3) + ((pr & 3) << 1) + ((pr >> 2) & 1);
        const float* r0 = &g_V2[bh][2 * pr][quad * 16];
#pragma unroll
        for (int c4 = 0; c4 < 4; c4++) {
            float4 a4 = *(const float4*)(r0 + c4 * 4);
            float4 b4 = *(const float4*)(r0 + DD + c4 * 4);
            float ar[4] = {a4.x, a4.y, a4.z, a4.w};
            float br[4] = {b4.x, b4.y, b4.z, b4.w};
#pragma unroll
            for (int i = 0; i < 4; i++) {
                int d = quad * 16 + c4 * 4 + i;
                uint32_t h, l;
                split2h(ar[i] * ISC, br[i] * ISC, h, l);
                BsH[d][w] = h;
                BsL[d][w] = l;
            }
        }
    }
    __syncthreads();

    float acc[8][4];
#pragma unroll
    for (int j = 0; j < 8; j++)
#pragma unroll
        for (int i = 0; i < 4; i++) acc[j][i] = 0.0f;

#pragma unroll
    for (int ks = 0; ks < 8; ks++) {
        uint4 aH = *(const uint4*)&g_WiPHi[nt * 8 + warp][ks][lane][0];
        uint4 aL = *(const uint4*)&g_WiPLo[nt * 8 + warp][ks][lane][0];
#pragma unroll
        for (int j = 0; j < 8; j++) {
            uint2 bH = *(const uint2*)&BsH[j * 8 + g][ks * 8 + 2 * tq];
            uint2 bL = *(const uint2*)&BsL[j * 8 + g][ks * 8 + 2 * tq];
            mma16816h(acc[j], aH, bH);
            mma16816h(acc[j], aH, bL);
            mma16816h(acc[j], aL, bH);
        }
    }

    const int m0 = warp * 16;
    float* ob = out + ((size_t)bh * LL + (size_t)nt * 128) * DD;
#pragma unroll
    for (int j = 0; j < 8; j++) {
        float* dst = &ob[(m0 + g) * DD + j * 8 + 2 * tq];
        *(float2*)dst = make_float2(acc[j][0], acc[j][1]);
        *(float2*)(dst + 8 * DD) = make_float2(acc[j][2], acc[j][3]);
    }
}

// ---------------- entry point ----------------
extern "C" void kernel_launch(void* const* d_in, const int* in_sizes, int n_in,
                              void* d_out, int out_size) {
    const float* q  = (const float*)d_in[0];
    const float* k  = (const float*)d_in[1];
    const float* v  = (const float*)d_in[2];
    const int* iq   = (const int*)d_in[3];
    const int* ik   = (const int*)d_in[4];
    const int* iv   = (const int*)d_in[5];
    float* out      = (float*)d_out;

    perm_kernel<<<1, 32>>>(iq, ik, iv);
    build_packed<<<1024, 256>>>(iq, ik, iv);

    const int fwd_smem = 2 * 4 * FWD_BUF_WORDS * 4;   // 81920 B
    cudaFuncSetAttribute(fwd_mma, cudaFuncAttributeMaxDynamicSharedMemorySize, fwd_smem);
    fwd_mma<<<dim3(NSPLIT, BH, 3), 256, fwd_smem>>>(q, k, v);

    reduce_kernel<<<1536, 256>>>();

    const int attn_smem = (2 * MM + 32 + 2 * 16) * SP * (int)sizeof(float);  // 83200 B
    cudaFuncSetAttribute(attn_kernel, cudaFuncAttributeMaxDynamicSharedMemorySize, attn_smem);
    attn_kernel<<<dim3(BH, 4), 256, attn_smem>>>();

    inv_mma<<<dim3(32, 64), 256>>>(out);
}

// round 8
// speedup vs baseline: 1.3062x; 1.3062x over previous
#include <cuda_runtime.h>
#include <cuda_fp16.h>
#include <math.h>
#include <cstdint>

#define LL    4096
#define DD    64
#define MODES 64
#define BH    64
#define MM    128
#define NSPLIT 4
#define SCALE 0.125f

// ---------------- globals (no allocation) ----------------
__device__ int      g_perm[3][64];                  // parity-sorted mode order per tensor
__device__ int      g_sclass[3][4];                 // strip class: 0=even 1=odd 2=mixed
__device__ int      g_vmap[64];                     // sigma_v^-1 o sigma_k
__device__ uint32_t g_WfPHi[3][8][2][64][32][4];    // fwd basis frags (K=1024), parity variant
__device__ uint32_t g_WfPLo[3][8][2][64][32][4];
__device__ uint32_t g_WiCcHi[128][4][32][4];        // inv cos basis frags (x1024 scaled)
__device__ uint32_t g_WiCcLo[128][4][32][4];
__device__ uint32_t g_WiCsHi[128][4][32][4];        // inv -sin basis frags
__device__ uint32_t g_WiCsLo[128][4][32][4];
__device__ float    g_F[3][NSPLIT][BH][MM][DD];     // split-K partials (storage mode order)
__device__ float    g_Ffin[3][BH][MM][DD];          // reduced spectra
__device__ float    g_V2[BH][MM][DD];               // post-attention values

// ---------------- helpers ----------------
__device__ __forceinline__ uint32_t packh(__half a, __half b) {
    return (uint32_t)__half_as_ushort(a) | ((uint32_t)__half_as_ushort(b) << 16);
}
__device__ __forceinline__ void split2h(float a, float b, uint32_t& h, uint32_t& l) {
    __half ha = __float2half_rn(a), hb = __float2half_rn(b);
    __half la = __float2half_rn(a - __half2float(ha));
    __half lb = __float2half_rn(b - __half2float(hb));
    h = packh(ha, hb);
    l = packh(la, lb);
}
__device__ __forceinline__ void mma16816h(float* c, const uint4& a, const uint2& b) {
    asm volatile(
        "mma.sync.aligned.m16n8k16.row.col.f32.f16.f16.f32 "
        "{%0,%1,%2,%3}, {%4,%5,%6,%7}, {%8,%9}, {%0,%1,%2,%3};"
        : "+f"(c[0]), "+f"(c[1]), "+f"(c[2]), "+f"(c[3])
        : "r"(a.x), "r"(a.y), "r"(a.z), "r"(a.w), "r"(b.x), "r"(b.y));
}

// ---------------- kernel 0: permutations (tiny, serial) ----------------
__global__ void perm_kernel(const int* __restrict__ iq,
                            const int* __restrict__ ik,
                            const int* __restrict__ iv) {
    if (threadIdx.x != 0) return;
    for (int t = 0; t < 3; t++) {
        const int* ix = (t == 0) ? iq : ((t == 1) ? ik : iv);
        int pm[64], ne = 0;
        for (int i = 0; i < 64; i++) if ((ix[i] & 1) == 0) pm[ne++] = i;
        int no = ne;
        for (int i = 0; i < 64; i++) if (ix[i] & 1) pm[no++] = i;
        for (int i = 0; i < 64; i++) g_perm[t][i] = pm[i];
        for (int s4 = 0; s4 < 4; s4++) {
            int st0 = s4 * 16, st1 = st0 + 15;
            g_sclass[t][s4] = (st1 < ne) ? 0 : ((st0 >= ne) ? 1 : 2);
        }
    }
    int ipv[64];
    for (int i = 0; i < 64; i++) ipv[g_perm[2][i]] = i;
    for (int s4 = 0; s4 < 64; s4++) g_vmap[s4] = ipv[g_perm[1][s4]];
}

// ---------------- kernel 1: build fragment-packed bases ----------------
#define FWDN (3 * 8 * 2 * 64 * 32 * 4)   // 393216
#define INVN (2 * 128 * 4 * 32 * 4)      // 131072

__global__ __launch_bounds__(256) void build_packed(const int* __restrict__ iq,
                                                    const int* __restrict__ ik,
                                                    const int* __restrict__ iv) {
    for (int gid = blockIdx.x * blockDim.x + threadIdx.x; gid < FWDN + INVN;
         gid += gridDim.x * blockDim.x) {
        if (gid < FWDN) {
            int r    = gid & 3;
            int lane = (gid >> 2) & 31;
            int ks   = (gid >> 7) & 63;
            int vv   = (gid >> 13) & 1;
            int s    = (gid >> 14) & 7;
            int t    = gid >> 17;
            int m_local = s * 16 + (r & 1) * 8 + (lane >> 2);
            const int* ix = (t == 0) ? iq : ((t == 1) ? ik : iv);
            int f = ix[g_perm[t][m_local & 63]];
            float v0 = 0.0f, v1 = 0.0f;
            if ((f & 1) == vv) {
                int k = ks * 16 + ((r >> 1) & 1) * 8 + (lane & 3) * 2;   // n in [0,1024)
                int r1 = (f * k) & (LL - 1);
                int r2 = (r1 + f) & (LL - 1);
                float s1, c1, s2, c2;
                sincospif((float)r1 * (1.0f / 2048.0f), &s1, &c1);
                sincospif((float)r2 * (1.0f / 2048.0f), &s2, &c2);
                v0 = (m_local < MODES) ? c1 : -s1;
                v1 = (m_local < MODES) ? c2 : -s2;
            }
            uint32_t h, l;
            split2h(v0, v1, h, l);
            g_WfPHi[t][s][vv][ks][lane][r] = h;
            g_WfPLo[t][s][vv][ks][lane][r] = l;
        } else {
            int g2   = gid - FWDN;
            int r    = g2 & 3;
            int lane = (g2 >> 2) & 31;
            int ks   = (g2 >> 7) & 3;
            int st   = (g2 >> 9) & 127;
            int arr  = (g2 >> 16) & 1;       // 0 = cos, 1 = -sin
            int n  = st * 16 + (r & 1) * 8 + (lane >> 2);          // [0,2048)
            int k  = ks * 16 + ((r >> 1) & 1) * 8 + (lane & 3) * 2; // [0,64)
            float v0, v1;
            {
                int fb = g_perm[0][k];
                float cs = (fb == 0) ? 0.25f : 0.5f;   // 1024 * (1 or 2)/4096
                int r1 = (fb * n) & (LL - 1);
                float s1, c1;
                sincospif((float)r1 * (1.0f / 2048.0f), &s1, &c1);
                v0 = arr ? (-cs * s1) : (cs * c1);
            }
            {
                int fb = g_perm[0][k + 1];
                float cs = (fb == 0) ? 0.25f : 0.5f;
                int r1 = (fb * n) & (LL - 1);
                float s1, c1;
                sincospif((float)r1 * (1.0f / 2048.0f), &s1, &c1);
                v1 = arr ? (-cs * s1) : (cs * c1);
            }
            uint32_t h, l;
            split2h(v0, v1, h, l);
            if (arr == 0) { g_WiCcHi[st][ks][lane][r] = h; g_WiCcLo[st][ks][lane][r] = l; }
            else          { g_WiCsHi[st][ks][lane][r] = h; g_WiCsLo[st][ks][lane][r] = l; }
        }
    }
}

// ---------------- kernel 2: forward DFT (fold-by-4, fp16 3-pass, split-K) ---------
// K=1024 after reflection+parity fold. grid (NSPLIT, 64, 3), 256 threads = 8 warps.
// B variants: 0=re-even(u+y) 1=re-odd(u-y) 2=im-even(w+z) 3=im-odd(w-z).
#define FWD_BUF_WORDS 2560
__global__ __launch_bounds__(256) void fwd_mma(const float* __restrict__ q,
                                               const float* __restrict__ k_,
                                               const float* __restrict__ v_,
                                               const int* __restrict__ iq,
                                               const int* __restrict__ ik,
                                               const int* __restrict__ iv) {
    extern __shared__ uint32_t dsm[];
    const int split = blockIdx.x, bh = blockIdx.y, t = blockIdx.z;
    const float* xb = ((t == 0) ? q : ((t == 1) ? k_ : v_)) + (size_t)bh * LL * DD;
    const int tid = threadIdx.x, warp = tid >> 5, lane = tid & 31;
    const int g = lane >> 2, tq = lane & 3;
    const int s = (warp + bh + split) & 7;
    const int cls = g_sclass[t][s & 3];
    const int vbase = (s >= 4) ? 2 : 0;
    const int p = tid & 31, oct = tid >> 5;
    const int w = ((p >> 3) << 3) + ((p & 3) << 1) + ((p >> 2) & 1);

#define FARR(v_, hl) (dsm + ((hl) * 4 + (v_)) * FWD_BUF_WORDS)

    float acc[8][4];
#pragma unroll
    for (int j = 0; j < 8; j++)
#pragma unroll
        for (int i = 0; i < 4; i++) acc[j][i] = 0.0f;

    for (int ch = 0; ch < 4; ch++) {
        const int nn = split * 256 + ch * 64 + 2 * p;   // n (first of pair), in [0,1024)
        {
            const int mi0 = (LL - nn) & (LL - 1);       // mirror of nn (0 -> 0)
            const int mi1 = LL - 1 - nn;                // mirror of nn+1
            const float* pa  = xb + (size_t)nn * DD + oct * 8;
            const float* pr0 = xb + (size_t)mi0 * DD + oct * 8;
            const float* pr1 = xb + (size_t)mi1 * DD + oct * 8;
            const float* pc  = xb + (size_t)(2048 + nn) * DD + oct * 8;
            const float* pd0 = xb + (size_t)(2048 - nn) * DD + oct * 8;
            const float* pd1 = xb + (size_t)(2047 - nn) * DD + oct * 8;
            float4 x0, x1;
            x0 = *(const float4*)(pa);       x1 = *(const float4*)(pa + 4);
            float Aa[8] = {x0.x, x0.y, x0.z, x0.w, x1.x, x1.y, x1.z, x1.w};
            x0 = *(const float4*)(pa + DD);  x1 = *(const float4*)(pa + DD + 4);
            float Ab[8] = {x0.x, x0.y, x0.z, x0.w, x1.x, x1.y, x1.z, x1.w};
            x0 = *(const float4*)(pr0);      x1 = *(const float4*)(pr0 + 4);
            float Ra[8] = {x0.x, x0.y, x0.z, x0.w, x1.x, x1.y, x1.z, x1.w};
            x0 = *(const float4*)(pr1);      x1 = *(const float4*)(pr1 + 4);
            float Rb[8] = {x0.x, x0.y, x0.z, x0.w, x1.x, x1.y, x1.z, x1.w};
            x0 = *(const float4*)(pc);       x1 = *(const float4*)(pc + 4);
            float Ca[8] = {x0.x, x0.y, x0.z, x0.w, x1.x, x1.y, x1.z, x1.w};
            x0 = *(const float4*)(pc + DD);  x1 = *(const float4*)(pc + DD + 4);
            float Cb[8] = {x0.x, x0.y, x0.z, x0.w, x1.x, x1.y, x1.z, x1.w};
            x0 = *(const float4*)(pd0);      x1 = *(const float4*)(pd0 + 4);
            float Da[8] = {x0.x, x0.y, x0.z, x0.w, x1.x, x1.y, x1.z, x1.w};
            x0 = *(const float4*)(pd1);      x1 = *(const float4*)(pd1 + 4);
            float Db[8] = {x0.x, x0.y, x0.z, x0.w, x1.x, x1.y, x1.z, x1.w};

            const float sc = (nn == 0) ? 0.5f : 1.0f;
            uint32_t* B0H = FARR(0, 0); uint32_t* B0L = FARR(0, 1);
            uint32_t* B1H = FARR(1, 0); uint32_t* B1L = FARR(1, 1);
            uint32_t* B2H = FARR(2, 0); uint32_t* B2L = FARR(2, 1);
            uint32_t* B3H = FARR(3, 0); uint32_t* B3L = FARR(3, 1);
#pragma unroll
            for (int i = 0; i < 8; i++) {
                float u0 = (Aa[i] + Ra[i]) * sc, w0 = Aa[i] - Ra[i];
                float y0 = (Ca[i] + Da[i]) * sc, z0 = Ca[i] - Da[i];
                float u1 = Ab[i] + Rb[i],        w1 = Ab[i] - Rb[i];
                float y1 = Cb[i] + Db[i],        z1 = Cb[i] - Db[i];
                int row = (oct * 8 + i) * 40 + w;
                uint32_t h, l;
                split2h(u0 + y0, u1 + y1, h, l); B0H[row] = h; B0L[row] = l;
                split2h(u0 - y0, u1 - y1, h, l); B1H[row] = h; B1L[row] = l;
                split2h(w0 + z0, w1 + z1, h, l); B2H[row] = h; B2L[row] = l;
                split2h(w0 - z0, w1 - z1, h, l); B3H[row] = h; B3L[row] = l;
            }
        }
        __syncthreads();
        const int ksg = split * 16 + ch * 4;
#pragma unroll
        for (int ks4 = 0; ks4 < 4; ks4++) {
            if (cls != 1) {
                uint4 aH = *(const uint4*)&g_WfPHi[t][s][0][ksg + ks4][lane][0];
                uint4 aL = *(const uint4*)&g_WfPLo[t][s][0][ksg + ks4][lane][0];
                const uint32_t* BH_ = FARR(vbase + 0, 0);
                const uint32_t* BL_ = FARR(vbase + 0, 1);
#pragma unroll
                for (int j = 0; j < 8; j++) {
                    uint2 bH = *(const uint2*)&BH_[(j * 8 + g) * 40 + ks4 * 8 + 2 * tq];
                    uint2 bL = *(const uint2*)&BL_[(j * 8 + g) * 40 + ks4 * 8 + 2 * tq];
                    mma16816h(acc[j], aH, bH);
                    mma16816h(acc[j], aH, bL);
                    mma16816h(acc[j], aL, bH);
                }
            }
            if (cls != 0) {
                uint4 aH = *(const uint4*)&g_WfPHi[t][s][1][ksg + ks4][lane][0];
                uint4 aL = *(const uint4*)&g_WfPLo[t][s][1][ksg + ks4][lane][0];
                const uint32_t* BH_ = FARR(vbase + 1, 0);
                const uint32_t* BL_ = FARR(vbase + 1, 1);
#pragma unroll
                for (int j = 0; j < 8; j++) {
                    uint2 bH = *(const uint2*)&BH_[(j * 8 + g) * 40 + ks4 * 8 + 2 * tq];
                    uint2 bL = *(const uint2*)&BL_[(j * 8 + g) * 40 + ks4 * 8 + 2 * tq];
                    mma16816h(acc[j], aH, bH);
                    mma16816h(acc[j], aH, bL);
                    mma16816h(acc[j], aL, bH);
                }
            }
        }
        __syncthreads();
    }

    const int m0 = s * 16;
    // rank-1 correction for samples x[1024], x[3072] (added once, in split 0)
    if (split == 0) {
        const int* ix = (t == 0) ? iq : ((t == 1) ? ik : iv);
        const bool is_im = (s >= 4);
        int f0 = ix[g_perm[t][(m0 + g) & 63]];
        int f1 = ix[g_perm[t][(m0 + g + 8) & 63]];
        float s0f, s1f;
        if (!is_im) {
            s0f = (f0 & 1) ? 0.0f : (((f0 >> 1) & 1) ? -1.0f : 1.0f);
            s1f = (f1 & 1) ? 0.0f : (((f1 >> 1) & 1) ? -1.0f : 1.0f);
        } else {
            s0f = (f0 & 1) ? (((f0 & 3) == 1) ? -1.0f : 1.0f) : 0.0f;
            s1f = (f1 & 1) ? (((f1 & 3) == 1) ? -1.0f : 1.0f) : 0.0f;
        }
        const float sgn = is_im ? -1.0f : 1.0f;
#pragma unroll
        for (int j = 0; j < 8; j++) {
            int d0 = j * 8 + 2 * tq;
            float2 u1 = *(const float2*)(xb + (size_t)1024 * DD + d0);
            float2 u3 = *(const float2*)(xb + (size_t)3072 * DD + d0);
            float uc0 = u1.x + sgn * u3.x;
            float uc1 = u1.y + sgn * u3.y;
            acc[j][0] += s0f * uc0; acc[j][1] += s0f * uc1;
            acc[j][2] += s1f * uc0; acc[j][3] += s1f * uc1;
        }
    }
#pragma unroll
    for (int j = 0; j < 8; j++) {
        float* dst = &g_F[t][split][bh][m0 + g][j * 8 + 2 * tq];
        *(float2*)dst = make_float2(acc[j][0], acc[j][1]);
        *(float2*)(dst + 8 * DD) = make_float2(acc[j][2], acc[j][3]);
    }
#undef FARR
}

// ---------------- kernel 3: reduce split-K partials ----------------
__global__ __launch_bounds__(256) void reduce_kernel() {
    const int TOT = 3 * BH * MM * DD / 4;
    int i = blockIdx.x * blockDim.x + threadIdx.x;
    if (i >= TOT) return;
    const int PER_T = BH * MM * DD / 4;
    int t = i / PER_T;
    int r = i - t * PER_T;
    const float4* base = (const float4*)&g_F[t][0][0][0][0];
    float4 a = base[r];
#pragma unroll
    for (int s = 1; s < NSPLIT; s++) {
        float4 b = base[s * PER_T + r];
        a.x += b.x; a.y += b.y; a.z += b.z; a.w += b.w;
    }
    ((float4*)g_Ffin)[i] = a;
}

// ---------------- kernel 4: complex attention (mode-split 4-way) ----------------
#define SP 65
__global__ __launch_bounds__(256) void attn_kernel() {
    extern __shared__ float sm[];
    float* Ks = sm;                 // [128][65]
    float* Vs = Ks + MM * SP;       // [128][65]
    float* Qs = Vs + MM * SP;       // [32][65]
    float* SR = Qs + 32 * SP;       // [16][65]
    float* SI = SR + 16 * SP;       // [16][65]

    const int bh = blockIdx.x, ms = blockIdx.y;
    const int tid = threadIdx.x;

    for (int e = tid; e < MM * DD; e += 256) {
        const int r = e >> 6, d = e & 63;
        Ks[r * SP + d] = g_Ffin[1][bh][r][d];
        int vrow = ((r >= 64) ? 64 : 0) + __ldg(&g_vmap[r & 63]);
        Vs[r * SP + d] = g_Ffin[2][bh][vrow][d];
    }
    for (int e = tid; e < 32 * DD; e += 256) {
        const int r = e >> 6, d = e & 63;
        int qrow = (r < 16) ? (ms * 16 + r) : (64 + ms * 16 + (r - 16));
        Qs[r * SP + d] = g_Ffin[0][bh][qrow][d];
    }
    __syncthreads();

    const int tm = tid >> 4;
    const int tn = tid & 15;

    {
        float re[4], im[4];
#pragma unroll
        for (int j = 0; j < 4; j++) { re[j] = 0.f; im[j] = 0.f; }
        for (int d = 0; d < DD; d++) {
            float qr = Qs[tm * SP + d];
            float qi = Qs[(16 + tm) * SP + d];
#pragma unroll
            for (int j = 0; j < 4; j++) {
                float kr = Ks[(tn * 4 + j) * SP + d];
                float ki = Ks[(64 + tn * 4 + j) * SP + d];
                re[j] = fmaf(qr, kr, re[j]);
                re[j] = fmaf(-qi, ki, re[j]);
                im[j] = fmaf(qr, ki, im[j]);
                im[j] = fmaf(qi, kr, im[j]);
            }
        }
#pragma unroll
        for (int j = 0; j < 4; j++) {
            const float x  = re[j] * SCALE;
            const float y  = im[j] * SCALE;
            const float x2 = 2.0f * x;
            float tr, ti;
            if (fabsf(x2) > 80.0f) {
                tr = (x > 0.0f) ? 1.0f : -1.0f;
                ti = 0.0f;
            } else {
                const float y2 = 2.0f * y;
                const float dn = coshf(x2) + cosf(y2);
                tr = sinhf(x2) / dn;
                ti = sinf(y2) / dn;
            }
            SR[tm * SP + tn * 4 + j] = tr;
            SI[tm * SP + tn * 4 + j] = ti;
        }
    }
    __syncthreads();

    {
        float vr[4], vi[4];
#pragma unroll
        for (int j = 0; j < 4; j++) { vr[j] = 0.f; vi[j] = 0.f; }
        for (int n = 0; n < MODES; n++) {
            float sr = SR[tm * SP + n];
            float si = SI[tm * SP + n];
#pragma unroll
            for (int j = 0; j < 4; j++) {
                float br = Vs[n * SP + tn * 4 + j];
                float bi = Vs[(64 + n) * SP + tn * 4 + j];
                vr[j] = fmaf(sr, br, vr[j]);
                vr[j] = fmaf(-si, bi, vr[j]);
                vi[j] = fmaf(sr, bi, vi[j]);
                vi[j] = fmaf(si, br, vi[j]);
            }
        }
#pragma unroll
        for (int j = 0; j < 4; j++) {
            g_V2[bh][ms * 16 + tm][tn * 4 + j]      = vr[j];
            g_V2[bh][64 + ms * 16 + tm][tn * 4 + j] = vi[j];
        }
    }
}

// ---------------- kernel 5: inverse transform (mirror trick, fp16 3-pass) ---------
// n in [0,2048): out[n] = Cc+Cs, out[4096-n] = Cc-Cs. grid (16, 64).
#define ISC (1.0f / 1024.0f)
__global__ __launch_bounds__(256) void inv_mma(float* __restrict__ out) {
    __shared__ uint32_t BsH[64][72];
    __shared__ uint32_t BsL[64][72];
    const int nt = blockIdx.x, bh = blockIdx.y;
    const int tid = threadIdx.x, warp = tid >> 5, lane = tid & 31;
    const int g = lane >> 2, tq = lane & 3;

    {
        const int pr = tid & 63, quad = tid >> 6;
        const int w = ((pr >> 3) << 3) + ((pr & 3) << 1) + ((pr >> 2) & 1);
        const float* r0 = &g_V2[bh][2 * pr][quad * 16];
#pragma unroll
        for (int c4 = 0; c4 < 4; c4++) {
            float4 a4 = *(const float4*)(r0 + c4 * 4);
            float4 b4 = *(const float4*)(r0 + DD + c4 * 4);
            float ar[4] = {a4.x, a4.y, a4.z, a4.w};
            float br[4] = {b4.x, b4.y, b4.z, b4.w};
#pragma unroll
            for (int i = 0; i < 4; i++) {
                int d = quad * 16 + c4 * 4 + i;
                uint32_t h, l;
                split2h(ar[i] * ISC, br[i] * ISC, h, l);
                BsH[d][w] = h;
                BsL[d][w] = l;
            }
        }
    }
    __syncthreads();

    float accC[8][4], accS[8][4];
#pragma unroll
    for (int j = 0; j < 8; j++)
#pragma unroll
        for (int i = 0; i < 4; i++) { accC[j][i] = 0.0f; accS[j][i] = 0.0f; }

    const int st = nt * 8 + warp;
#pragma unroll
    for (int ks = 0; ks < 4; ks++) {
        uint4 aHc = *(const uint4*)&g_WiCcHi[st][ks][lane][0];
        uint4 aLc = *(const uint4*)&g_WiCcLo[st][ks][lane][0];
        uint4 aHs = *(const uint4*)&g_WiCsHi[st][ks][lane][0];
        uint4 aLs = *(const uint4*)&g_WiCsLo[st][ks][lane][0];
#pragma unroll
        for (int j = 0; j < 8; j++) {
            uint2 bHc = *(const uint2*)&BsH[j * 8 + g][ks * 8 + 2 * tq];
            uint2 bLc = *(const uint2*)&BsL[j * 8 + g][ks * 8 + 2 * tq];
            uint2 bHs = *(const uint2*)&BsH[j * 8 + g][(ks + 4) * 8 + 2 * tq];
            uint2 bLs = *(const uint2*)&BsL[j * 8 + g][(ks + 4) * 8 + 2 * tq];
            mma16816h(accC[j], aHc, bHc);
            mma16816h(accC[j], aHc, bLc);
            mma16816h(accC[j], aLc, bHc);
            mma16816h(accS[j], aHs, bHs);
            mma16816h(accS[j], aHs, bLs);
            mma16816h(accS[j], aLs, bHs);
        }
    }

    const int n0r = nt * 128 + warp * 16;
    float* ob = out + (size_t)bh * LL * DD;
#pragma unroll
    for (int j = 0; j < 8; j++) {
        const int d0 = j * 8 + 2 * tq;
        const int na = n0r + g, nb = n0r + g + 8;
        *(float2*)(ob + (size_t)na * DD + d0) =
            make_float2(accC[j][0] + accS[j][0], accC[j][1] + accS[j][1]);
        if (na != 0)
            *(float2*)(ob + (size_t)(LL - na) * DD + d0) =
                make_float2(accC[j][0] - accS[j][0], accC[j][1] - accS[j][1]);
        *(float2*)(ob + (size_t)nb * DD + d0) =
            make_float2(accC[j][2] + accS[j][2], accC[j][3] + accS[j][3]);
        *(float2*)(ob + (size_t)(LL - nb) * DD + d0) =
            make_float2(accC[j][2] - accS[j][2], accC[j][3] - accS[j][3]);
    }
    // out[2048] = sum_k c_k * (-1)^{f_k} * Vr[k][d]   (sin term = 0)
    if (nt == 0 && tid < 64) {
        const int d = tid;
        float sum = 0.0f;
#pragma unroll 8
        for (int k = 0; k < 64; k++) {
            int fb = g_perm[0][k];
            float c = (fb == 0) ? (1.0f / 4096.0f) : (2.0f / 4096.0f);
            float sg = (fb & 1) ? -c : c;
            sum += sg * g_V2[bh][k][d];
        }
        ob[(size_t)2048 * DD + d] = sum;
    }
}

// ---------------- entry point ----------------
extern "C" void kernel_launch(void* const* d_in, const int* in_sizes, int n_in,
                              void* d_out, int out_size) {
    const float* q  = (const float*)d_in[0];
    const float* k  = (const float*)d_in[1];
    const float* v  = (const float*)d_in[2];
    const int* iq   = (const int*)d_in[3];
    const int* ik   = (const int*)d_in[4];
    const int* iv   = (const int*)d_in[5];
    float* out      = (float*)d_out;

    perm_kernel<<<1, 32>>>(iq, ik, iv);
    build_packed<<<1024, 256>>>(iq, ik, iv);

    const int fwd_smem = 8 * FWD_BUF_WORDS * 4;   // 81920 B
    cudaFuncSetAttribute(fwd_mma, cudaFuncAttributeMaxDynamicSharedMemorySize, fwd_smem);
    fwd_mma<<<dim3(NSPLIT, BH, 3), 256, fwd_smem>>>(q, k, v, iq, ik, iv);

    reduce_kernel<<<1536, 256>>>();

    const int attn_smem = (2 * MM + 32 + 2 * 16) * SP * (int)sizeof(float);  // 83200 B
    cudaFuncSetAttribute(attn_kernel, cudaFuncAttributeMaxDynamicSharedMemorySize, attn_smem);
    attn_kernel<<<dim3(BH, 4), 256, attn_smem>>>();

    inv_mma<<<dim3(16, 64), 256>>>(out);
}

// round 9
// speedup vs baseline: 1.3337x; 1.0210x over previous
#include <cuda_runtime.h>
#include <cuda_fp16.h>
#include <math.h>
#include <cstdint>

#define LL    4096
#define DD    64
#define MODES 64
#define BH    64
#define MM    128
#define NSPLIT 4
#define SCALE 0.125f

// ---------------- globals (no allocation) ----------------
__device__ float2   g_tab[LL];                      // cos/sin(2*pi*r/4096), fp32-exact
__device__ int      g_perm[3][64];                  // parity-sorted mode order per tensor
__device__ int      g_sclass[3][4];                 // strip class: 0=even 1=odd 2=mixed
__device__ int      g_vmap[64];                     // sigma_v^-1 o sigma_k
__device__ uint32_t g_WfPHi[3][8][2][64][32][4];    // fwd basis frags (K=1024), parity variant
__device__ uint32_t g_WfPLo[3][8][2][64][32][4];
__device__ uint32_t g_WiCcHi[128][4][32][4];        // inv cos basis frags (x1024 scaled)
__device__ uint32_t g_WiCcLo[128][4][32][4];
__device__ uint32_t g_WiCsHi[128][4][32][4];        // inv -sin basis frags
__device__ uint32_t g_WiCsLo[128][4][32][4];
__device__ float    g_F[3][NSPLIT][BH][MM][DD];     // split-K partials (storage mode order)
__device__ float    g_V2[BH][MM][DD];               // post-attention values

// ---------------- helpers ----------------
__device__ __forceinline__ uint32_t packh(__half a, __half b) {
    return (uint32_t)__half_as_ushort(a) | ((uint32_t)__half_as_ushort(b) << 16);
}
__device__ __forceinline__ void split2h(float a, float b, uint32_t& h, uint32_t& l) {
    __half ha = __float2half_rn(a), hb = __float2half_rn(b);
    __half la = __float2half_rn(a - __half2float(ha));
    __half lb = __float2half_rn(b - __half2float(hb));
    h = packh(ha, hb);
    l = packh(la, lb);
}
__device__ __forceinline__ void mma16816h(float* c, const uint4& a, const uint2& b) {
    asm volatile(
        "mma.sync.aligned.m16n8k16.row.col.f32.f16.f16.f32 "
        "{%0,%1,%2,%3}, {%4,%5,%6,%7}, {%8,%9}, {%0,%1,%2,%3};"
        : "+f"(c[0]), "+f"(c[1]), "+f"(c[2]), "+f"(c[3])
        : "r"(a.x), "r"(a.y), "r"(a.z), "r"(a.w), "r"(b.x), "r"(b.y));
}

// ---------------- kernel 0: phase table + permutations ----------------
__global__ __launch_bounds__(256) void tab_kernel(const int* __restrict__ iq,
                                                  const int* __restrict__ ik,
                                                  const int* __restrict__ iv) {
    int r = blockIdx.x * blockDim.x + threadIdx.x;
    if (r < LL) {
        float s, c;
        sincospif((float)r * (1.0f / 2048.0f), &s, &c);
        g_tab[r] = make_float2(c, s);
    }
    if (blockIdx.x == 0 && threadIdx.x == 0) {
        for (int t = 0; t < 3; t++) {
            const int* ix = (t == 0) ? iq : ((t == 1) ? ik : iv);
            int pm[64], ne = 0;
            for (int i = 0; i < 64; i++) if ((ix[i] & 1) == 0) pm[ne++] = i;
            int no = ne;
            for (int i = 0; i < 64; i++) if (ix[i] & 1) pm[no++] = i;
            for (int i = 0; i < 64; i++) g_perm[t][i] = pm[i];
            for (int s4 = 0; s4 < 4; s4++) {
                int st0 = s4 * 16, st1 = st0 + 15;
                g_sclass[t][s4] = (st1 < ne) ? 0 : ((st0 >= ne) ? 1 : 2);
            }
        }
        int ipv[64];
        for (int i = 0; i < 64; i++) ipv[g_perm[2][i]] = i;
        for (int s4 = 0; s4 < 64; s4++) g_vmap[s4] = ipv[g_perm[1][s4]];
    }
}

// ---------------- kernel 1: build fragment-packed bases (table-driven) ------------
#define FWDN (3 * 8 * 2 * 64 * 32 * 4)   // 393216
#define INVN (2 * 128 * 4 * 32 * 4)      // 131072

__global__ __launch_bounds__(256) void build_packed(const int* __restrict__ iq,
                                                    const int* __restrict__ ik,
                                                    const int* __restrict__ iv) {
    for (int gid = blockIdx.x * blockDim.x + threadIdx.x; gid < FWDN + INVN;
         gid += gridDim.x * blockDim.x) {
        if (gid < FWDN) {
            int r    = gid & 3;
            int lane = (gid >> 2) & 31;
            int ks   = (gid >> 7) & 63;
            int vv   = (gid >> 13) & 1;
            int s    = (gid >> 14) & 7;
            int t    = gid >> 17;
            int m_local = s * 16 + (r & 1) * 8 + (lane >> 2);
            const int* ix = (t == 0) ? iq : ((t == 1) ? ik : iv);
            int f = ix[g_perm[t][m_local & 63]];
            float v0 = 0.0f, v1 = 0.0f;
            if ((f & 1) == vv) {
                int k = ks * 16 + ((r >> 1) & 1) * 8 + (lane & 3) * 2;   // n in [0,1024)
                int r1 = (f * k) & (LL - 1);
                int r2 = (r1 + f) & (LL - 1);
                float2 c1 = g_tab[r1], c2 = g_tab[r2];
                v0 = (m_local < MODES) ? c1.x : -c1.y;
                v1 = (m_local < MODES) ? c2.x : -c2.y;
            }
            uint32_t h, l;
            split2h(v0, v1, h, l);
            g_WfPHi[t][s][vv][ks][lane][r] = h;
            g_WfPLo[t][s][vv][ks][lane][r] = l;
        } else {
            int g2   = gid - FWDN;
            int r    = g2 & 3;
            int lane = (g2 >> 2) & 31;
            int ks   = (g2 >> 7) & 3;
            int st   = (g2 >> 9) & 127;
            int arr  = (g2 >> 16) & 1;       // 0 = cos, 1 = -sin
            int n  = st * 16 + (r & 1) * 8 + (lane >> 2);          // [0,2048)
            int k  = ks * 16 + ((r >> 1) & 1) * 8 + (lane & 3) * 2; // [0,64)
            float v0, v1;
            {
                int fb = g_perm[0][k];
                float cs = (fb == 0) ? 0.25f : 0.5f;   // 1024 * (1 or 2)/4096
                float2 c1 = g_tab[(fb * n) & (LL - 1)];
                v0 = arr ? (-cs * c1.y) : (cs * c1.x);
            }
            {
                int fb = g_perm[0][k + 1];
                float cs = (fb == 0) ? 0.25f : 0.5f;
                float2 c1 = g_tab[(fb * n) & (LL - 1)];
                v1 = arr ? (-cs * c1.y) : (cs * c1.x);
            }
            uint32_t h, l;
            split2h(v0, v1, h, l);
            if (arr == 0) { g_WiCcHi[st][ks][lane][r] = h; g_WiCcLo[st][ks][lane][r] = l; }
            else          { g_WiCsHi[st][ks][lane][r] = h; g_WiCsLo[st][ks][lane][r] = l; }
        }
    }
}

// ---------------- kernel 2: forward DFT (fold-by-4, fp16 3-pass, split-K) ---------
#define FWD_BUF_WORDS 2560
__global__ __launch_bounds__(256) void fwd_mma(const float* __restrict__ q,
                                               const float* __restrict__ k_,
                                               const float* __restrict__ v_,
                                               const int* __restrict__ iq,
                                               const int* __restrict__ ik,
                                               const int* __restrict__ iv) {
    extern __shared__ uint32_t dsm[];
    const int split = blockIdx.x, bh = blockIdx.y, t = blockIdx.z;
    const float* xb = ((t == 0) ? q : ((t == 1) ? k_ : v_)) + (size_t)bh * LL * DD;
    const int tid = threadIdx.x, warp = tid >> 5, lane = tid & 31;
    const int g = lane >> 2, tq = lane & 3;
    const int s = (warp + bh + split) & 7;
    const int cls = g_sclass[t][s & 3];
    const int vbase = (s >= 4) ? 2 : 0;
    const int p = tid & 31, oct = tid >> 5;
    const int w = ((p >> 3) << 3) + ((p & 3) << 1) + ((p >> 2) & 1);

#define FARR(v_, hl) (dsm + ((hl) * 4 + (v_)) * FWD_BUF_WORDS)

    float acc[8][4];
#pragma unroll
    for (int j = 0; j < 8; j++)
#pragma unroll
        for (int i = 0; i < 4; i++) acc[j][i] = 0.0f;

    for (int ch = 0; ch < 4; ch++) {
        const int nn = split * 256 + ch * 64 + 2 * p;   // n (first of pair), in [0,1024)
        {
            const int mi0 = (LL - nn) & (LL - 1);
            const int mi1 = LL - 1 - nn;
            const float* pa  = xb + (size_t)nn * DD + oct * 8;
            const float* pr0 = xb + (size_t)mi0 * DD + oct * 8;
            const float* pr1 = xb + (size_t)mi1 * DD + oct * 8;
            const float* pc  = xb + (size_t)(2048 + nn) * DD + oct * 8;
            const float* pd0 = xb + (size_t)(2048 - nn) * DD + oct * 8;
            const float* pd1 = xb + (size_t)(2047 - nn) * DD + oct * 8;
            float4 x0, x1;
            x0 = *(const float4*)(pa);       x1 = *(const float4*)(pa + 4);
            float Aa[8] = {x0.x, x0.y, x0.z, x0.w, x1.x, x1.y, x1.z, x1.w};
            x0 = *(const float4*)(pa + DD);  x1 = *(const float4*)(pa + DD + 4);
            float Ab[8] = {x0.x, x0.y, x0.z, x0.w, x1.x, x1.y, x1.z, x1.w};
            x0 = *(const float4*)(pr0);      x1 = *(const float4*)(pr0 + 4);
            float Ra[8] = {x0.x, x0.y, x0.z, x0.w, x1.x, x1.y, x1.z, x1.w};
            x0 = *(const float4*)(pr1);      x1 = *(const float4*)(pr1 + 4);
            float Rb[8] = {x0.x, x0.y, x0.z, x0.w, x1.x, x1.y, x1.z, x1.w};
            x0 = *(const float4*)(pc);       x1 = *(const float4*)(pc + 4);
            float Ca[8] = {x0.x, x0.y, x0.z, x0.w, x1.x, x1.y, x1.z, x1.w};
            x0 = *(const float4*)(pc + DD);  x1 = *(const float4*)(pc + DD + 4);
            float Cb[8] = {x0.x, x0.y, x0.z, x0.w, x1.x, x1.y, x1.z, x1.w};
            x0 = *(const float4*)(pd0);      x1 = *(const float4*)(pd0 + 4);
            float Da[8] = {x0.x, x0.y, x0.z, x0.w, x1.x, x1.y, x1.z, x1.w};
            x0 = *(const float4*)(pd1);      x1 = *(const float4*)(pd1 + 4);
            float Db[8] = {x0.x, x0.y, x0.z, x0.w, x1.x, x1.y, x1.z, x1.w};

            const float sc = (nn == 0) ? 0.5f : 1.0f;
            uint32_t* B0H = FARR(0, 0); uint32_t* B0L = FARR(0, 1);
            uint32_t* B1H = FARR(1, 0); uint32_t* B1L = FARR(1, 1);
            uint32_t* B2H = FARR(2, 0); uint32_t* B2L = FARR(2, 1);
            uint32_t* B3H = FARR(3, 0); uint32_t* B3L = FARR(3, 1);
#pragma unroll
            for (int i = 0; i < 8; i++) {
                float u0 = (Aa[i] + Ra[i]) * sc, w0 = Aa[i] - Ra[i];
                float y0 = (Ca[i] + Da[i]) * sc, z0 = Ca[i] - Da[i];
                float u1 = Ab[i] + Rb[i],        w1 = Ab[i] - Rb[i];
                float y1 = Cb[i] + Db[i],        z1 = Cb[i] - Db[i];
                int row = (oct * 8 + i) * 40 + w;
                uint32_t h, l;
                split2h(u0 + y0, u1 + y1, h, l); B0H[row] = h; B0L[row] = l;
                split2h(u0 - y0, u1 - y1, h, l); B1H[row] = h; B1L[row] = l;
                split2h(w0 + z0, w1 + z1, h, l); B2H[row] = h; B2L[row] = l;
                split2h(w0 - z0, w1 - z1, h, l); B3H[row] = h; B3L[row] = l;
            }
        }
        __syncthreads();
        const int ksg = split * 16 + ch * 4;
#pragma unroll
        for (int ks4 = 0; ks4 < 4; ks4++) {
            if (cls != 1) {
                uint4 aH = *(const uint4*)&g_WfPHi[t][s][0][ksg + ks4][lane][0];
                uint4 aL = *(const uint4*)&g_WfPLo[t][s][0][ksg + ks4][lane][0];
                const uint32_t* BH_ = FARR(vbase + 0, 0);
                const uint32_t* BL_ = FARR(vbase + 0, 1);
#pragma unroll
                for (int j = 0; j < 8; j++) {
                    uint2 bH = *(const uint2*)&BH_[(j * 8 + g) * 40 + ks4 * 8 + 2 * tq];
                    uint2 bL = *(const uint2*)&BL_[(j * 8 + g) * 40 + ks4 * 8 + 2 * tq];
                    mma16816h(acc[j], aH, bH);
                    mma16816h(acc[j], aH, bL);
                    mma16816h(acc[j], aL, bH);
                }
            }
            if (cls != 0) {
                uint4 aH = *(const uint4*)&g_WfPHi[t][s][1][ksg + ks4][lane][0];
                uint4 aL = *(const uint4*)&g_WfPLo[t][s][1][ksg + ks4][lane][0];
                const uint32_t* BH_ = FARR(vbase + 1, 0);
                const uint32_t* BL_ = FARR(vbase + 1, 1);
#pragma unroll
                for (int j = 0; j < 8; j++) {
                    uint2 bH = *(const uint2*)&BH_[(j * 8 + g) * 40 + ks4 * 8 + 2 * tq];
                    uint2 bL = *(const uint2*)&BL_[(j * 8 + g) * 40 + ks4 * 8 + 2 * tq];
                    mma16816h(acc[j], aH, bH);
                    mma16816h(acc[j], aH, bL);
                    mma16816h(acc[j], aL, bH);
                }
            }
        }
        __syncthreads();
    }

    const int m0 = s * 16;
    // rank-1 correction for samples x[1024], x[3072] (added once, in split 0)
    if (split == 0) {
        const int* ix = (t == 0) ? iq : ((t == 1) ? ik : iv);
        const bool is_im = (s >= 4);
        int f0 = ix[g_perm[t][(m0 + g) & 63]];
        int f1 = ix[g_perm[t][(m0 + g + 8) & 63]];
        float s0f, s1f;
        if (!is_im) {
            s0f = (f0 & 1) ? 0.0f : (((f0 >> 1) & 1) ? -1.0f : 1.0f);
            s1f = (f1 & 1) ? 0.0f : (((f1 >> 1) & 1) ? -1.0f : 1.0f);
        } else {
            s0f = (f0 & 1) ? (((f0 & 3) == 1) ? -1.0f : 1.0f) : 0.0f;
            s1f = (f1 & 1) ? (((f1 & 3) == 1) ? -1.0f : 1.0f) : 0.0f;
        }
        const float sgn = is_im ? -1.0f : 1.0f;
#pragma unroll
        for (int j = 0; j < 8; j++) {
            int d0 = j * 8 + 2 * tq;
            float2 u1 = *(const float2*)(xb + (size_t)1024 * DD + d0);
            float2 u3 = *(const float2*)(xb + (size_t)3072 * DD + d0);
            float uc0 = u1.x + sgn * u3.x;
            float uc1 = u1.y + sgn * u3.y;
            acc[j][0] += s0f * uc0; acc[j][1] += s0f * uc1;
            acc[j][2] += s1f * uc0; acc[j][3] += s1f * uc1;
        }
    }
#pragma unroll
    for (int j = 0; j < 8; j++) {
        float* dst = &g_F[t][split][bh][m0 + g][j * 8 + 2 * tq];
        *(float2*)dst = make_float2(acc[j][0], acc[j][1]);
        *(float2*)(dst + 8 * DD) = make_float2(acc[j][2], acc[j][3]);
    }
#undef FARR
}

// ---------------- kernel 3: complex attention (mode-split 4-way, fused reduce) ----
#define SP 65
__device__ __forceinline__ float4 sum_splits4(const float* base) {
    const size_t STR = (size_t)BH * MM * DD;
    float4 a = *(const float4*)(base);
#pragma unroll
    for (int s = 1; s < NSPLIT; s++) {
        float4 b = *(const float4*)(base + s * STR);
        a.x += b.x; a.y += b.y; a.z += b.z; a.w += b.w;
    }
    return a;
}

__global__ __launch_bounds__(256) void attn_kernel() {
    extern __shared__ float sm[];
    float* Ks = sm;                 // [128][65]
    float* Vs = Ks + MM * SP;       // [128][65]
    float* Qs = Vs + MM * SP;       // [32][65]
    float* SR = Qs + 32 * SP;       // [16][65]
    float* SI = SR + 16 * SP;       // [16][65]

    const int bh = blockIdx.x, ms = blockIdx.y;
    const int tid = threadIdx.x;

    for (int e = tid; e < MM * 16; e += 256) {
        const int r = e >> 4, d4 = (e & 15) * 4;
        float4 kk = sum_splits4(&g_F[1][0][bh][r][d4]);
        int vrow = ((r >= 64) ? 64 : 0) + __ldg(&g_vmap[r & 63]);
        float4 vv = sum_splits4(&g_F[2][0][bh][vrow][d4]);
        float* kd = &Ks[r * SP + d4];
        kd[0] = kk.x; kd[1] = kk.y; kd[2] = kk.z; kd[3] = kk.w;
        float* vd = &Vs[r * SP + d4];
        vd[0] = vv.x; vd[1] = vv.y; vd[2] = vv.z; vd[3] = vv.w;
    }
    for (int e = tid; e < 32 * 16; e += 256) {
        const int r = e >> 4, d4 = (e & 15) * 4;
        int qrow = (r < 16) ? (ms * 16 + r) : (64 + ms * 16 + (r - 16));
        float4 qq = sum_splits4(&g_F[0][0][bh][qrow][d4]);
        float* qd = &Qs[r * SP + d4];
        qd[0] = qq.x; qd[1] = qq.y; qd[2] = qq.z; qd[3] = qq.w;
    }
    __syncthreads();

    const int tm = tid >> 4;
    const int tn = tid & 15;

    {
        float re[4], im[4];
#pragma unroll
        for (int j = 0; j < 4; j++) { re[j] = 0.f; im[j] = 0.f; }
        for (int d = 0; d < DD; d++) {
            float qr = Qs[tm * SP + d];
            float qi = Qs[(16 + tm) * SP + d];
#pragma unroll
            for (int j = 0; j < 4; j++) {
                float kr = Ks[(tn * 4 + j) * SP + d];
                float ki = Ks[(64 + tn * 4 + j) * SP + d];
                re[j] = fmaf(qr, kr, re[j]);
                re[j] = fmaf(-qi, ki, re[j]);
                im[j] = fmaf(qr, ki, im[j]);
                im[j] = fmaf(qi, kr, im[j]);
            }
        }
#pragma unroll
        for (int j = 0; j < 4; j++) {
            const float x  = re[j] * SCALE;
            const float y  = im[j] * SCALE;
            const float x2 = 2.0f * x;
            float tr, ti;
            if (fabsf(x2) > 80.0f) {
                tr = (x > 0.0f) ? 1.0f : -1.0f;
                ti = 0.0f;
            } else {
                const float y2 = 2.0f * y;
                const float dn = coshf(x2) + cosf(y2);
                tr = sinhf(x2) / dn;
                ti = sinf(y2) / dn;
            }
            SR[tm * SP + tn * 4 + j] = tr;
            SI[tm * SP + tn * 4 + j] = ti;
        }
    }
    __syncthreads();

    {
        float vr[4], vi[4];
#pragma unroll
        for (int j = 0; j < 4; j++) { vr[j] = 0.f; vi[j] = 0.f; }
        for (int n = 0; n < MODES; n++) {
            float sr = SR[tm * SP + n];
            float si = SI[tm * SP + n];
#pragma unroll
            for (int j = 0; j < 4; j++) {
                float br = Vs[n * SP + tn * 4 + j];
                float bi = Vs[(64 + n) * SP + tn * 4 + j];
                vr[j] = fmaf(sr, br, vr[j]);
                vr[j] = fmaf(-si, bi, vr[j]);
                vi[j] = fmaf(sr, bi, vi[j]);
                vi[j] = fmaf(si, br, vi[j]);
            }
        }
#pragma unroll
        for (int j = 0; j < 4; j++) {
            g_V2[bh][ms * 16 + tm][tn * 4 + j]      = vr[j];
            g_V2[bh][64 + ms * 16 + tm][tn * 4 + j] = vi[j];
        }
    }
}

// ---------------- kernel 4: inverse transform (mirror trick, fp16 3-pass) ---------
#define ISC (1.0f / 1024.0f)
__global__ __launch_bounds__(256) void inv_mma(float* __restrict__ out) {
    __shared__ uint32_t BsH[64][72];
    __shared__ uint32_t BsL[64][72];
    const int nt = blockIdx.x, bh = blockIdx.y;
    const int tid = threadIdx.x, warp = tid >> 5, lane = tid & 31;
    const int g = lane >> 2, tq = lane & 3;

    {
        const int pr = tid & 63, quad = tid >> 6;
        const int w = ((pr >> 3) << 3) + ((pr & 3) << 1) + ((pr >> 2) & 1);
        const float* r0 = &g_V2[bh][2 * pr][quad * 16];
#pragma unroll
        for (int c4 = 0; c4 < 4; c4++) {
            float4 a4 = *(const float4*)(r0 + c4 * 4);
            float4 b4 = *(const float4*)(r0 + DD + c4 * 4);
            float ar[4] = {a4.x, a4.y, a4.z, a4.w};
            float br[4] = {b4.x, b4.y, b4.z, b4.w};
#pragma unroll
            for (int i = 0; i < 4; i++) {
                int d = quad * 16 + c4 * 4 + i;
                uint32_t h, l;
                split2h(ar[i] * ISC, br[i] * ISC, h, l);
                BsH[d][w] = h;
                BsL[d][w] = l;
            }
        }
    }
    __syncthreads();

    float accC[8][4], accS[8][4];
#pragma unroll
    for (int j = 0; j < 8; j++)
#pragma unroll
        for (int i = 0; i < 4; i++) { accC[j][i] = 0.0f; accS[j][i] = 0.0f; }

    const int st = nt * 8 + warp;
#pragma unroll
    for (int ks = 0; ks < 4; ks++) {
        uint4 aHc = *(const uint4*)&g_WiCcHi[st][ks][lane][0];
        uint4 aLc = *(const uint4*)&g_WiCcLo[st][ks][lane][0];
        uint4 aHs = *(const uint4*)&g_WiCsHi[st][ks][lane][0];
        uint4 aLs = *(const uint4*)&g_WiCsLo[st][ks][lane][0];
#pragma unroll
        for (int j = 0; j < 8; j++) {
            uint2 bHc = *(const uint2*)&BsH[j * 8 + g][ks * 8 + 2 * tq];
            uint2 bLc = *(const uint2*)&BsL[j * 8 + g][ks * 8 + 2 * tq];
            uint2 bHs = *(const uint2*)&BsH[j * 8 + g][(ks + 4) * 8 + 2 * tq];
            uint2 bLs = *(const uint2*)&BsL[j * 8 + g][(ks + 4) * 8 + 2 * tq];
            mma16816h(accC[j], aHc, bHc);
            mma16816h(accC[j], aHc, bLc);
            mma16816h(accC[j], aLc, bHc);
            mma16816h(accS[j], aHs, bHs);
            mma16816h(accS[j], aHs, bLs);
            mma16816h(accS[j], aLs, bHs);
        }
    }

    const int n0r = nt * 128 + warp * 16;
    float* ob = out + (size_t)bh * LL * DD;
#pragma unroll
    for (int j = 0; j < 8; j++) {
        const int d0 = j * 8 + 2 * tq;
        const int na = n0r + g, nb = n0r + g + 8;
        *(float2*)(ob + (size_t)na * DD + d0) =
            make_float2(accC[j][0] + accS[j][0], accC[j][1] + accS[j][1]);
        if (na != 0)
            *(float2*)(ob + (size_t)(LL - na) * DD + d0) =
                make_float2(accC[j][0] - accS[j][0], accC[j][1] - accS[j][1]);
        *(float2*)(ob + (size_t)nb * DD + d0) =
            make_float2(accC[j][2] + accS[j][2], accC[j][3] + accS[j][3]);
        *(float2*)(ob + (size_t)(LL - nb) * DD + d0) =
            make_float2(accC[j][2] - accS[j][2], accC[j][3] - accS[j][3]);
    }
    // out[2048] = sum_k c_k * (-1)^{f_k} * Vr[k][d]   (sin term = 0)
    if (nt == 0 && tid < 64) {
        const int d = tid;
        float sum = 0.0f;
#pragma unroll 8
        for (int k = 0; k < 64; k++) {
            int fb = g_perm[0][k];
            float c = (fb == 0) ? (1.0f / 4096.0f) : (2.0f / 4096.0f);
            float sg = (fb & 1) ? -c : c;
            sum += sg * g_V2[bh][k][d];
        }
        ob[(size_t)2048 * DD + d] = sum;
    }
}

// ---------------- entry point ----------------
extern "C" void kernel_launch(void* const* d_in, const int* in_sizes, int n_in,
                              void* d_out, int out_size) {
    const float* q  = (const float*)d_in[0];
    const float* k  = (const float*)d_in[1];
    const float* v  = (const float*)d_in[2];
    const int* iq   = (const int*)d_in[3];
    const int* ik   = (const int*)d_in[4];
    const int* iv   = (const int*)d_in[5];
    float* out      = (float*)d_out;

    tab_kernel<<<16, 256>>>(iq, ik, iv);
    build_packed<<<1024, 256>>>(iq, ik, iv);

    const int fwd_smem = 8 * FWD_BUF_WORDS * 4;   // 81920 B
    cudaFuncSetAttribute(fwd_mma, cudaFuncAttributeMaxDynamicSharedMemorySize, fwd_smem);
    fwd_mma<<<dim3(NSPLIT, BH, 3), 256, fwd_smem>>>(q, k, v, iq, ik, iv);

    const int attn_smem = (2 * MM + 32 + 2 * 16) * SP * (int)sizeof(float);  // 83200 B
    cudaFuncSetAttribute(attn_kernel, cudaFuncAttributeMaxDynamicSharedMemorySize, attn_smem);
    attn_kernel<<<dim3(BH, 4), 256, attn_smem>>>();

    inv_mma<<<dim3(16, 64), 256>>>(out);
}